// round 9
// baseline (speedup 1.0000x reference)
#include <cuda_runtime.h>
#include <cstdint>

// EMA scan via TRUNCATED PARALLEL LOOKBACK (single pass, minimal traffic,
// no serial chain).  out[b,0,c]=x[b,0,c]; out[b,t,c]=0.1*x + 0.9*out[b,t-1,c].
// Shape (16, 4096, 512) fp32.
//
// Block = 64 timesteps x 256 channels (half of C=512); 512 thr = 8 seg x 64 cg.
// Each block computes its ZERO-INIT chunk aggregate (independent of all other
// blocks) and publishes it immediately. Decay 0.9^128 ~ 1.4e-6 means
//   cin_k = agg_{k-1} + B64 * agg_{k-2}          (exact for k<=2)
// suffices — no dependency chain, waits are only scheduling skew.
// Bounded spin + warmup-re-read fallback keeps it hang-proof.

namespace {
constexpr int T      = 4096;
constexpr int C4     = 128;             // float4 channel groups (512 ch)
constexpr int SEGS   = 8;
constexpr int PSTEPS = 8;
constexpr int CGB    = 64;              // channel-groups per block
constexpr int CHUNK  = SEGS * PSTEPS;   // 64 timesteps per block
constexpr int NCHUNK = T / CHUNK;       // 64
constexpr int NCHAIN = 16 * 2;          // batches x channel-halves
constexpr float A  = 0.1f;
constexpr float Bc = 0.9f;
constexpr int MAXSPIN = 8192;           // bounded wait -> no hang possible

constexpr float fpow(float b, int n) { float r = 1.0f; for (int i = 0; i < n; ++i) r *= b; return r; }
constexpr float B8  = fpow(Bc, 8);
constexpr float B12 = fpow(Bc, 12);
constexpr float B64 = fpow(Bc, 64);
}

__device__ unsigned g_flags[NCHAIN][NCHUNK];           // zero-init; self-resetting
__device__ float4   g_agg[NCHAIN][NCHUNK][CGB];        // zero-init chunk aggregates

__constant__ float B8S[SEGS] = {
    fpow(Bc, 0),  fpow(Bc, 8),  fpow(Bc, 16), fpow(Bc, 24),
    fpow(Bc, 32), fpow(Bc, 40), fpow(Bc, 48), fpow(Bc, 56)
};
__constant__ float BPOW[PSTEPS] = {
    fpow(Bc, 1), fpow(Bc, 2), fpow(Bc, 3), fpow(Bc, 4),
    fpow(Bc, 5), fpow(Bc, 6), fpow(Bc, 7), fpow(Bc, 8)
};

__device__ __forceinline__ float4 fma4(float s, const float4 a, const float4 b) {
    // s*a + b
    float4 r;
    r.x = fmaf(s, a.x, b.x);
    r.y = fmaf(s, a.y, b.y);
    r.z = fmaf(s, a.z, b.z);
    r.w = fmaf(s, a.w, b.w);
    return r;
}

__global__ __launch_bounds__(512, 2) void ema_lookback_kernel(
    const float4* __restrict__ x, float4* __restrict__ out)
{
    __shared__ float4   s_segL[SEGS][CGB];
    __shared__ float4   s_pref[SEGS + 1][CGB];
    __shared__ float4   s_cin[CGB];
    __shared__ unsigned s_ok;

    const int tid   = threadIdx.x;
    const int cg    = tid & (CGB - 1);
    const int seg   = tid >> 6;
    const int chain = blockIdx.x;           // 0..31  (b*2 + half)
    const int chunk = blockIdx.y;           // 0..63  (slow dim -> bid order)
    const int b     = chain >> 1;
    const int half  = chain & 1;
    const int cgg   = half * CGB + cg;

    const int    t0    = chunk * CHUNK;
    const int    tbase = t0 + seg * PSTEPS;
    const size_t gbase = ((size_t)b * T + tbase) * C4 + cgg;

    // ---- load 8 timesteps (streaming; each x element read exactly once) ----
    float4 v[PSTEPS];
    const float4* xp = x + gbase;
    #pragma unroll
    for (int i = 0; i < PSTEPS; ++i) v[i] = __ldcs(xp + (size_t)i * C4);

    // ---- zero-init local EMA, in place ----
    const bool first = (chunk == 0 && seg == 0);
    if (!first) { v[0].x *= A; v[0].y *= A; v[0].z *= A; v[0].w *= A; }
    // (global t=0: out[0] = x[0], absorbed into local with carry_in = 0)
    #pragma unroll
    for (int i = 1; i < PSTEPS; ++i) {
        v[i].x = fmaf(Bc, v[i-1].x, A * v[i].x);
        v[i].y = fmaf(Bc, v[i-1].y, A * v[i].y);
        v[i].z = fmaf(Bc, v[i-1].z, A * v[i].z);
        v[i].w = fmaf(Bc, v[i-1].w, A * v[i].w);
    }

    s_segL[seg][cg] = v[PSTEPS - 1];
    __syncthreads();

    // ---- segment prefix compose (seg-0 threads, one per channel-group) ----
    if (seg == 0) {
        float4 c = make_float4(0.f, 0.f, 0.f, 0.f);
        #pragma unroll
        for (int s = 0; s < SEGS; ++s) {
            s_pref[s][cg] = c;
            c = fma4(B8, c, s_segL[s][cg]);   // c = segL + B8*c
        }
        s_pref[SEGS][cg] = c;                 // zero-init chunk aggregate
    }
    __syncthreads();

    // ---- publish our aggregate IMMEDIATELY (independent of predecessors) ----
    if (chunk < NCHUNK - 1 && seg == SEGS - 1) {
        const float4 agg = s_pref[SEGS][cg];
        asm volatile("st.global.cg.v4.f32 [%0], {%1,%2,%3,%4};"
                     :: "l"(&g_agg[chain][chunk][cg]),
                        "f"(agg.x), "f"(agg.y), "f"(agg.z), "f"(agg.w) : "memory");
    }
    __syncthreads();
    if (tid == 0 && chunk < NCHUNK - 1) {
        __threadfence();
        asm volatile("st.release.gpu.u32 [%0], %1;"
                     :: "l"(&g_flags[chain][chunk]), "r"(1u) : "memory");
    }

    // ---- lookback: cin = agg_{k-1} + B64 * agg_{k-2}  (truncated, ~1.4e-6) ----
    float4 cin = make_float4(0.f, 0.f, 0.f, 0.f);
    if (chunk > 0) {
        if (tid == 0) {
            unsigned ok = 1, f;
            #pragma unroll
            for (int d = 1; d <= 2; ++d) {
                if (chunk - d < 0) break;
                const unsigned* fp = &g_flags[chain][chunk - d];
                f = 0;
                for (int it = 0; it < MAXSPIN; ++it) {
                    asm volatile("ld.acquire.gpu.u32 %0, [%1];" : "=r"(f) : "l"(fp) : "memory");
                    if (f) break;
                    __nanosleep(32);
                }
                ok &= f;
            }
            s_ok = ok;
        }
        __syncthreads();

        if (s_ok) {
            float4 a1;
            asm volatile("ld.global.cg.v4.f32 {%0,%1,%2,%3}, [%4];"
                         : "=f"(a1.x), "=f"(a1.y), "=f"(a1.z), "=f"(a1.w)
                         : "l"(&g_agg[chain][chunk - 1][cg]));
            cin = a1;
            if (chunk > 1) {
                float4 a2;
                asm volatile("ld.global.cg.v4.f32 {%0,%1,%2,%3}, [%4];"
                             : "=f"(a2.x), "=f"(a2.y), "=f"(a2.z), "=f"(a2.w)
                             : "l"(&g_agg[chain][chunk - 2][cg]));
                cin = fma4(B64, a2, a1);
            }
        } else {
            // Fallback: reconstruct carry from a warmup window (never hangs).
            // W=64 (exact, includes t=0) for chunk 1; W=96 (0.9^96 ~ 4e-5) else.
            const int W_eff = (chunk == 1) ? 64 : 96;
            const int PW    = W_eff / SEGS;              // 8 or 12
            const float cB  = (chunk == 1) ? B8 : B12;   // B^PW
            const bool inc0 = (chunk == 1);              // window starts at t=0
            const float4* wp = x + ((size_t)b * T + (t0 - W_eff + seg * PW)) * C4 + cgg;
            float4 c = make_float4(0.f, 0.f, 0.f, 0.f);
            #pragma unroll 4
            for (int i = 0; i < PW; ++i) {
                float4 w = __ldg(wp + (size_t)i * C4);
                float a0 = (inc0 && seg == 0 && i == 0) ? 1.0f : A;
                c.x = fmaf(Bc, c.x, a0 * w.x);
                c.y = fmaf(Bc, c.y, a0 * w.y);
                c.z = fmaf(Bc, c.z, a0 * w.z);
                c.w = fmaf(Bc, c.w, a0 * w.w);
            }
            s_segL[seg][cg] = c;
            __syncthreads();
            if (seg == 0) {
                float4 cc = make_float4(0.f, 0.f, 0.f, 0.f);
                #pragma unroll
                for (int s = 0; s < SEGS; ++s)
                    cc = fma4(cB, cc, s_segL[s][cg]);
                s_cin[cg] = cc;
            }
            __syncthreads();
            cin = s_cin[cg];
        }

        // ---- replay-safe flag reset by each flag's LAST reader ----
        __syncthreads();                         // all agg reads done
        if (tid == 0) {
            if (chunk >= 2)          g_flags[chain][chunk - 2] = 0;
            if (chunk == NCHUNK - 1) g_flags[chain][chunk - 1] = 0;
        }
    }

    // ---- finalize: out[t] = local[t] + B^(t+1) * seg_carry ----
    const float4 cs = fma4(B8S[seg], cin, s_pref[seg][cg]);

    float4* op = out + gbase;
    #pragma unroll
    for (int i = 0; i < PSTEPS; ++i) {
        __stcs(op + (size_t)i * C4, fma4(BPOW[i], cs, v[i]));
    }
}

extern "C" void kernel_launch(void* const* d_in, const int* in_sizes, int n_in,
                              void* d_out, int out_size)
{
    const float4* x = (const float4*)d_in[0];
    float4* out = (float4*)d_out;
    dim3 grid(NCHAIN, NCHUNK);   // chunk = slow dim -> predecessors get lower bids
    ema_lookback_kernel<<<grid, 512>>>(x, out);
}

// round 12
// speedup vs baseline: 35.0519x; 35.0519x over previous
#include <cuda_runtime.h>
#include <cstdint>

// EMA scan via TRUNCATED PARALLEL LOOKBACK (single pass, minimal traffic).
// out[b,0,c]=x[b,0,c]; out[b,t,c]=0.1*x + 0.9*out[b,t-1,c].  (16,4096,512) fp32.
//
// Block = 64 timesteps x 256 channels; 512 thr = 8 seg x 64 float4-groups.
// Each block publishes its ZERO-INIT chunk aggregate immediately (independent
// of all other blocks).  0.9^128 ~ 1.4e-6  =>  cin_k = agg_{k-1} + B64*agg_{k-2}.
//
// Round-9 lesson: in-kernel flag resets race with readers (a reset could land
// before the d=1 reader's poll -> full-MAXSPIN 2ms stall). Fix: flags are
// zeroed by a cudaMemsetAsync node BEFORE the kernel; flags are monotone 0->1
// within a launch, so no race exists. Bounded spin + warmup fallback keeps it
// hang-proof under any block scheduling.

namespace {
constexpr int T      = 4096;
constexpr int C4     = 128;             // float4 channel groups (512 ch)
constexpr int SEGS   = 8;
constexpr int PSTEPS = 8;
constexpr int CGB    = 64;              // channel-groups per block
constexpr int CHUNK  = SEGS * PSTEPS;   // 64 timesteps per block
constexpr int NCHUNK = T / CHUNK;       // 64
constexpr int NCHAIN = 16 * 2;          // batches x channel-halves
constexpr float A  = 0.1f;
constexpr float Bc = 0.9f;
constexpr int MAXSPIN = 2048;           // bounded wait -> no hang possible

constexpr float fpow(float b, int n) { float r = 1.0f; for (int i = 0; i < n; ++i) r *= b; return r; }
constexpr float B8  = fpow(Bc, 8);
constexpr float B12 = fpow(Bc, 12);
constexpr float B64 = fpow(Bc, 64);
}

__device__ unsigned g_flags[NCHAIN][NCHUNK];           // zeroed by memset node each launch
__device__ float4   g_agg[NCHAIN][NCHUNK][CGB];        // zero-init chunk aggregates

__constant__ float B8S[SEGS] = {
    fpow(Bc, 0),  fpow(Bc, 8),  fpow(Bc, 16), fpow(Bc, 24),
    fpow(Bc, 32), fpow(Bc, 40), fpow(Bc, 48), fpow(Bc, 56)
};
__constant__ float BPOW[PSTEPS] = {
    fpow(Bc, 1), fpow(Bc, 2), fpow(Bc, 3), fpow(Bc, 4),
    fpow(Bc, 5), fpow(Bc, 6), fpow(Bc, 7), fpow(Bc, 8)
};

__device__ __forceinline__ float4 fma4(float s, const float4 a, const float4 b) {
    // s*a + b
    float4 r;
    r.x = fmaf(s, a.x, b.x);
    r.y = fmaf(s, a.y, b.y);
    r.z = fmaf(s, a.z, b.z);
    r.w = fmaf(s, a.w, b.w);
    return r;
}

__global__ __launch_bounds__(512, 2) void ema_lookback_kernel(
    const float4* __restrict__ x, float4* __restrict__ out)
{
    __shared__ float4   s_segL[SEGS][CGB];
    __shared__ float4   s_pref[SEGS + 1][CGB];
    __shared__ float4   s_cin[CGB];
    __shared__ unsigned s_ok;

    const int tid   = threadIdx.x;
    const int cg    = tid & (CGB - 1);
    const int seg   = tid >> 6;
    const int chain = blockIdx.x;           // 0..31  (b*2 + half)
    const int chunk = blockIdx.y;           // 0..63  (slow dim -> bid order)
    const int b     = chain >> 1;
    const int half  = chain & 1;
    const int cgg   = half * CGB + cg;

    const int    t0    = chunk * CHUNK;
    const int    tbase = t0 + seg * PSTEPS;
    const size_t gbase = ((size_t)b * T + tbase) * C4 + cgg;

    // ---- load 8 timesteps (streaming; each x element read exactly once) ----
    float4 v[PSTEPS];
    const float4* xp = x + gbase;
    #pragma unroll
    for (int i = 0; i < PSTEPS; ++i) v[i] = __ldcs(xp + (size_t)i * C4);

    // ---- zero-init local EMA, in place ----
    const bool first = (chunk == 0 && seg == 0);
    if (!first) { v[0].x *= A; v[0].y *= A; v[0].z *= A; v[0].w *= A; }
    // (global t=0: out[0] = x[0], absorbed into local with carry_in = 0)
    #pragma unroll
    for (int i = 1; i < PSTEPS; ++i) {
        v[i].x = fmaf(Bc, v[i-1].x, A * v[i].x);
        v[i].y = fmaf(Bc, v[i-1].y, A * v[i].y);
        v[i].z = fmaf(Bc, v[i-1].z, A * v[i].z);
        v[i].w = fmaf(Bc, v[i-1].w, A * v[i].w);
    }

    s_segL[seg][cg] = v[PSTEPS - 1];
    __syncthreads();

    // ---- segment prefix compose (seg-0 threads, one per channel-group) ----
    if (seg == 0) {
        float4 c = make_float4(0.f, 0.f, 0.f, 0.f);
        #pragma unroll
        for (int s = 0; s < SEGS; ++s) {
            s_pref[s][cg] = c;
            c = fma4(B8, c, s_segL[s][cg]);   // c = segL + B8*c
        }
        s_pref[SEGS][cg] = c;                 // zero-init chunk aggregate
    }
    __syncthreads();

    // ---- publish our aggregate IMMEDIATELY (independent of predecessors) ----
    if (chunk < NCHUNK - 1 && seg == SEGS - 1) {
        const float4 agg = s_pref[SEGS][cg];
        asm volatile("st.global.cg.v4.f32 [%0], {%1,%2,%3,%4};"
                     :: "l"(&g_agg[chain][chunk][cg]),
                        "f"(agg.x), "f"(agg.y), "f"(agg.z), "f"(agg.w) : "memory");
    }
    __syncthreads();
    if (tid == 0 && chunk < NCHUNK - 1) {
        __threadfence();
        asm volatile("st.release.gpu.u32 [%0], %1;"
                     :: "l"(&g_flags[chain][chunk]), "r"(1u) : "memory");
    }

    // ---- lookback: cin = agg_{k-1} + B64 * agg_{k-2}  (truncated, ~1.4e-6) ----
    float4 cin = make_float4(0.f, 0.f, 0.f, 0.f);
    if (chunk > 0) {
        if (tid == 0) {
            unsigned ok = 1;
            #pragma unroll
            for (int d = 1; d <= 2; ++d) {
                if (chunk - d < 0) break;
                const unsigned* fp = &g_flags[chain][chunk - d];
                unsigned f = 0;
                for (int it = 0; it < MAXSPIN; ++it) {
                    asm volatile("ld.acquire.gpu.u32 %0, [%1];" : "=r"(f) : "l"(fp) : "memory");
                    if (f) break;
                    __nanosleep(64);
                }
                ok &= f;
            }
            s_ok = ok;
        }
        __syncthreads();

        if (s_ok) {
            float4 a1;
            asm volatile("ld.global.cg.v4.f32 {%0,%1,%2,%3}, [%4];"
                         : "=f"(a1.x), "=f"(a1.y), "=f"(a1.z), "=f"(a1.w)
                         : "l"(&g_agg[chain][chunk - 1][cg]));
            cin = a1;
            if (chunk > 1) {
                float4 a2;
                asm volatile("ld.global.cg.v4.f32 {%0,%1,%2,%3}, [%4];"
                             : "=f"(a2.x), "=f"(a2.y), "=f"(a2.z), "=f"(a2.w)
                             : "l"(&g_agg[chain][chunk - 2][cg]));
                cin = fma4(B64, a2, a1);
            }
        } else {
            // Fallback: reconstruct carry from a warmup window (never hangs).
            // W=64 (exact, includes t=0) for chunk 1; W=96 (0.9^96 ~ 4e-5) else.
            const int W_eff = (chunk == 1) ? 64 : 96;
            const int PW    = W_eff / SEGS;              // 8 or 12
            const float cB  = (chunk == 1) ? B8 : B12;   // B^PW
            const bool inc0 = (chunk == 1);              // window starts at t=0
            const float4* wp = x + ((size_t)b * T + (t0 - W_eff + seg * PW)) * C4 + cgg;
            float4 c = make_float4(0.f, 0.f, 0.f, 0.f);
            #pragma unroll 4
            for (int i = 0; i < PW; ++i) {
                float4 w = __ldg(wp + (size_t)i * C4);
                float a0 = (inc0 && seg == 0 && i == 0) ? 1.0f : A;
                c.x = fmaf(Bc, c.x, a0 * w.x);
                c.y = fmaf(Bc, c.y, a0 * w.y);
                c.z = fmaf(Bc, c.z, a0 * w.z);
                c.w = fmaf(Bc, c.w, a0 * w.w);
            }
            s_segL[seg][cg] = c;
            __syncthreads();
            if (seg == 0) {
                float4 cc = make_float4(0.f, 0.f, 0.f, 0.f);
                #pragma unroll
                for (int s = 0; s < SEGS; ++s)
                    cc = fma4(cB, cc, s_segL[s][cg]);
                s_cin[cg] = cc;
            }
            __syncthreads();
            cin = s_cin[cg];
        }
    }

    // ---- finalize: out[t] = local[t] + B^(t+1) * seg_carry ----
    const float4 cs = fma4(B8S[seg], cin, s_pref[seg][cg]);

    float4* op = out + gbase;
    #pragma unroll
    for (int i = 0; i < PSTEPS; ++i) {
        __stcs(op + (size_t)i * C4, fma4(BPOW[i], cs, v[i]));
    }
}

extern "C" void kernel_launch(void* const* d_in, const int* in_sizes, int n_in,
                              void* d_out, int out_size)
{
    const float4* x = (const float4*)d_in[0];
    float4* out = (float4*)d_out;

    // Zero the flags in a separate graph node BEFORE the kernel: flags are
    // monotone 0->1 within a launch (no read/reset race), replay-safe.
    void* flags_ptr = nullptr;
    cudaGetSymbolAddress(&flags_ptr, g_flags);
    cudaMemsetAsync(flags_ptr, 0, sizeof(unsigned) * NCHAIN * NCHUNK);

    dim3 grid(NCHAIN, NCHUNK);   // chunk = slow dim -> predecessors get lower bids
    ema_lookback_kernel<<<grid, 512>>>(x, out);
}

// round 13
// speedup vs baseline: 37.8380x; 1.0795x over previous
#include <cuda_runtime.h>
#include <cstdint>

// EMA scan via TRUNCATED PARALLEL LOOKBACK (single pass, minimal traffic).
// out[b,0,c]=x[b,0,c]; out[b,t,c]=0.1*x + 0.9*out[b,t-1,c].  (16,4096,512) fp32.
//
// Block = 64 timesteps x 256 channels; 512 thr = 8 seg x 64 float4-groups.
// Each block publishes its ZERO-INIT chunk aggregate immediately (independent
// of all other blocks).  0.9^128 ~ 1.4e-6  =>  cin_k = agg_{k-1} + B64*agg_{k-2}.
//
// Sync: CONSUMER-CREDIT flags (self-resetting, no memset node needed).
//   publisher: st agg; fence; atomicAdd(flag, n_consumers)   [2, or 1 for k=62]
//   consumer:  poll flag>0 (acquire); read agg; atomicSub(flag, 1)
// Each consumer removes only its own credit -> a consumer polling after publish
// always sees >0 (no reset/read race). All flags return to 0 by launch end ->
// replay-safe with a single kernel node. Bounded spin + warmup fallback keeps
// it hang-proof under any block scheduling.

namespace {
constexpr int T      = 4096;
constexpr int C4     = 128;             // float4 channel groups (512 ch)
constexpr int SEGS   = 8;
constexpr int PSTEPS = 8;
constexpr int CGB    = 64;              // channel-groups per block
constexpr int CHUNK  = SEGS * PSTEPS;   // 64 timesteps per block
constexpr int NCHUNK = T / CHUNK;       // 64
constexpr int NCHAIN = 16 * 2;          // batches x channel-halves
constexpr float A  = 0.1f;
constexpr float Bc = 0.9f;
constexpr int MAXSPIN = 2048;           // bounded wait -> no hang possible

constexpr float fpow(float b, int n) { float r = 1.0f; for (int i = 0; i < n; ++i) r *= b; return r; }
constexpr float B8  = fpow(Bc, 8);
constexpr float B12 = fpow(Bc, 12);
constexpr float B64 = fpow(Bc, 64);
}

__device__ unsigned g_flags[NCHAIN][NCHUNK];           // credit counters; 0 at launch start & end
__device__ float4   g_agg[NCHAIN][NCHUNK][CGB];        // zero-init chunk aggregates

__constant__ float B8S[SEGS] = {
    fpow(Bc, 0),  fpow(Bc, 8),  fpow(Bc, 16), fpow(Bc, 24),
    fpow(Bc, 32), fpow(Bc, 40), fpow(Bc, 48), fpow(Bc, 56)
};
__constant__ float BPOW[PSTEPS] = {
    fpow(Bc, 1), fpow(Bc, 2), fpow(Bc, 3), fpow(Bc, 4),
    fpow(Bc, 5), fpow(Bc, 6), fpow(Bc, 7), fpow(Bc, 8)
};

__device__ __forceinline__ float4 fma4(float s, const float4 a, const float4 b) {
    // s*a + b
    float4 r;
    r.x = fmaf(s, a.x, b.x);
    r.y = fmaf(s, a.y, b.y);
    r.z = fmaf(s, a.z, b.z);
    r.w = fmaf(s, a.w, b.w);
    return r;
}

__global__ __launch_bounds__(512, 2) void ema_lookback_kernel(
    const float4* __restrict__ x, float4* __restrict__ out)
{
    __shared__ float4   s_segL[SEGS][CGB];
    __shared__ float4   s_pref[SEGS + 1][CGB];
    __shared__ float4   s_cin[CGB];
    __shared__ unsigned s_ok;

    const int tid   = threadIdx.x;
    const int cg    = tid & (CGB - 1);
    const int seg   = tid >> 6;
    const int chain = blockIdx.x;           // 0..31  (b*2 + half)
    const int chunk = blockIdx.y;           // 0..63  (slow dim -> bid order)
    const int b     = chain >> 1;
    const int half  = chain & 1;
    const int cgg   = half * CGB + cg;

    const int    t0    = chunk * CHUNK;
    const int    tbase = t0 + seg * PSTEPS;
    const size_t gbase = ((size_t)b * T + tbase) * C4 + cgg;

    // ---- load 8 timesteps (streaming; each x element read exactly once) ----
    float4 v[PSTEPS];
    const float4* xp = x + gbase;
    #pragma unroll
    for (int i = 0; i < PSTEPS; ++i) v[i] = __ldcs(xp + (size_t)i * C4);

    // ---- zero-init local EMA, in place ----
    const bool first = (chunk == 0 && seg == 0);
    if (!first) { v[0].x *= A; v[0].y *= A; v[0].z *= A; v[0].w *= A; }
    // (global t=0: out[0] = x[0], absorbed into local with carry_in = 0)
    #pragma unroll
    for (int i = 1; i < PSTEPS; ++i) {
        v[i].x = fmaf(Bc, v[i-1].x, A * v[i].x);
        v[i].y = fmaf(Bc, v[i-1].y, A * v[i].y);
        v[i].z = fmaf(Bc, v[i-1].z, A * v[i].z);
        v[i].w = fmaf(Bc, v[i-1].w, A * v[i].w);
    }

    s_segL[seg][cg] = v[PSTEPS - 1];
    __syncthreads();

    // ---- segment prefix compose (seg-0 threads, one per channel-group) ----
    if (seg == 0) {
        float4 c = make_float4(0.f, 0.f, 0.f, 0.f);
        #pragma unroll
        for (int s = 0; s < SEGS; ++s) {
            s_pref[s][cg] = c;
            c = fma4(B8, c, s_segL[s][cg]);   // c = segL + B8*c
        }
        s_pref[SEGS][cg] = c;                 // zero-init chunk aggregate
    }
    __syncthreads();

    // ---- publish our aggregate IMMEDIATELY (independent of predecessors) ----
    if (chunk < NCHUNK - 1 && seg == SEGS - 1) {
        const float4 agg = s_pref[SEGS][cg];
        asm volatile("st.global.cg.v4.f32 [%0], {%1,%2,%3,%4};"
                     :: "l"(&g_agg[chain][chunk][cg]),
                        "f"(agg.x), "f"(agg.y), "f"(agg.z), "f"(agg.w) : "memory");
    }
    __syncthreads();
    if (tid == 0 && chunk < NCHUNK - 1) {
        // credits = number of consumers of this aggregate (chunk+1, chunk+2)
        const unsigned credits = (chunk < NCHUNK - 2) ? 2u : 1u;
        __threadfence();
        atomicAdd(&g_flags[chain][chunk], credits);
    }

    // ---- lookback: cin = agg_{k-1} + B64 * agg_{k-2}  (truncated, ~1.4e-6) ----
    float4 cin = make_float4(0.f, 0.f, 0.f, 0.f);
    if (chunk > 0) {
        if (tid == 0) {
            unsigned ok = 1;
            #pragma unroll
            for (int d = 1; d <= 2; ++d) {
                if (chunk - d < 0) break;
                unsigned* fp = &g_flags[chain][chunk - d];
                unsigned f;
                // first poll without sleeping (common case: already published)
                asm volatile("ld.acquire.gpu.u32 %0, [%1];" : "=r"(f) : "l"(fp) : "memory");
                for (int it = 0; !f && it < MAXSPIN; ++it) {
                    __nanosleep(64);
                    asm volatile("ld.acquire.gpu.u32 %0, [%1];" : "=r"(f) : "l"(fp) : "memory");
                }
                ok &= (f != 0u);
            }
            s_ok = ok;
            if (ok) {
                // consume our credits (self-resetting flags; no reset/read race:
                // each consumer removes only its own credit)
                atomicSub(&g_flags[chain][chunk - 1], 1u);
                if (chunk > 1) atomicSub(&g_flags[chain][chunk - 2], 1u);
            }
        }
        __syncthreads();

        if (s_ok) {
            float4 a1;
            asm volatile("ld.global.cg.v4.f32 {%0,%1,%2,%3}, [%4];"
                         : "=f"(a1.x), "=f"(a1.y), "=f"(a1.z), "=f"(a1.w)
                         : "l"(&g_agg[chain][chunk - 1][cg]));
            cin = a1;
            if (chunk > 1) {
                float4 a2;
                asm volatile("ld.global.cg.v4.f32 {%0,%1,%2,%3}, [%4];"
                             : "=f"(a2.x), "=f"(a2.y), "=f"(a2.z), "=f"(a2.w)
                             : "l"(&g_agg[chain][chunk - 2][cg]));
                cin = fma4(B64, a2, a1);
            }
        } else {
            // Fallback: reconstruct carry from a warmup window (never hangs).
            // W=64 (exact, includes t=0) for chunk 1; W=96 (0.9^96 ~ 4e-5) else.
            const int W_eff = (chunk == 1) ? 64 : 96;
            const int PW    = W_eff / SEGS;              // 8 or 12
            const float cB  = (chunk == 1) ? B8 : B12;   // B^PW
            const bool inc0 = (chunk == 1);              // window starts at t=0
            const float4* wp = x + ((size_t)b * T + (t0 - W_eff + seg * PW)) * C4 + cgg;
            float4 c = make_float4(0.f, 0.f, 0.f, 0.f);
            #pragma unroll 4
            for (int i = 0; i < PW; ++i) {
                float4 w = __ldg(wp + (size_t)i * C4);
                float a0 = (inc0 && seg == 0 && i == 0) ? 1.0f : A;
                c.x = fmaf(Bc, c.x, a0 * w.x);
                c.y = fmaf(Bc, c.y, a0 * w.y);
                c.z = fmaf(Bc, c.z, a0 * w.z);
                c.w = fmaf(Bc, c.w, a0 * w.w);
            }
            s_segL[seg][cg] = c;
            __syncthreads();
            if (seg == 0) {
                float4 cc = make_float4(0.f, 0.f, 0.f, 0.f);
                #pragma unroll
                for (int s = 0; s < SEGS; ++s)
                    cc = fma4(cB, cc, s_segL[s][cg]);
                s_cin[cg] = cc;
            }
            __syncthreads();
            cin = s_cin[cg];
        }
    }

    // ---- finalize: out[t] = local[t] + B^(t+1) * seg_carry ----
    const float4 cs = fma4(B8S[seg], cin, s_pref[seg][cg]);

    float4* op = out + gbase;
    #pragma unroll
    for (int i = 0; i < PSTEPS; ++i) {
        __stcs(op + (size_t)i * C4, fma4(BPOW[i], cs, v[i]));
    }
}

extern "C" void kernel_launch(void* const* d_in, const int* in_sizes, int n_in,
                              void* d_out, int out_size)
{
    const float4* x = (const float4*)d_in[0];
    float4* out = (float4*)d_out;
    dim3 grid(NCHAIN, NCHUNK);   // chunk = slow dim -> predecessors get lower bids
    ema_lookback_kernel<<<grid, 512>>>(x, out);
}